// round 1
// baseline (speedup 1.0000x reference)
#include <cuda_runtime.h>
#include <cuda_bf16.h>

#define BATCH 8
#define CHAN 128

// Scratch (device globals — no allocation allowed)
__device__ float g_y64[BATCH * CHAN * 4096];   // 16 MB
__device__ float g_h64[BATCH * CHAN * 4096];   // 16 MB
__device__ float g_a32[BATCH * CHAN * 1024];   // 4 MB
__device__ float g_b32[BATCH * CHAN * 1024];   // 4 MB
__device__ float g_pool[BATCH * CHAN];

// ---------------------------------------------------------------------------
// Channel mix for the input layer: y[b,c,p] = sum_i lin[c,i] * x[b,i,p], Ci=3
// ---------------------------------------------------------------------------
__global__ void mix3_kernel(const float* __restrict__ x,
                            const float* __restrict__ lin,
                            float* __restrict__ out) {
    int idx = blockIdx.x * 256 + threadIdx.x;       // total = 8*128*4096
    int p = idx & 4095;
    int c = (idx >> 12) & 127;
    int b = idx >> 19;
    const float* xb = x + b * 3 * 4096 + p;
    float l0 = lin[c * 3 + 0], l1 = lin[c * 3 + 1], l2 = lin[c * 3 + 2];
    out[idx] = fmaf(l0, xb[0], fmaf(l1, xb[4096], l2 * xb[8192]));
}

// ---------------------------------------------------------------------------
// Channel mix 128x128: out[b,c,p] = sum_i L[c,i] * in[b,i,p]
// blockDim=128 (thread = output channel), TILE=64 pixels per block.
// L chunk staged in smem (padded, conflict-free per-lane reads); input tile
// staged in smem (uniform broadcast float4 reads). acc[64] in registers.
// ---------------------------------------------------------------------------
template <int HW>
__global__ void __launch_bounds__(128) mix128_kernel(const float* __restrict__ L,
                                                     const float* __restrict__ in,
                                                     float* __restrict__ out) {
    __shared__ float sL[128 * 33];   // 32 i-values per channel, pitch 33
    __shared__ float sh[32 * 64];    // 32 input channels x 64 pixels
    constexpr int TILE = 64;
    const int tilesPerImg = HW / TILE;
    const int b = blockIdx.x / tilesPerImg;
    const int px0 = (blockIdx.x % tilesPerImg) * TILE;
    const int c = threadIdx.x;

    float acc[TILE];
#pragma unroll
    for (int p = 0; p < TILE; p++) acc[p] = 0.f;

    for (int q = 0; q < 4; q++) {                   // 4 chunks of 32 input chans
        __syncthreads();
        // load L chunk: 128c x 32i (coalesced read, conflict-free write)
#pragma unroll
        for (int k = 0; k < 32; k++) {
            int idx = k * 128 + c;
            int cc = idx >> 5, ii = idx & 31;
            sL[cc * 33 + ii] = L[cc * 128 + q * 32 + ii];
        }
        // load input tile: 32i x 64p (coalesced)
#pragma unroll
        for (int k = 0; k < 16; k++) {
            int idx = k * 128 + c;
            int ii = idx >> 6, pp = idx & 63;
            sh[idx] = in[(b * 128 + q * 32 + ii) * HW + px0 + pp];
        }
        __syncthreads();
#pragma unroll 2
        for (int i = 0; i < 32; i++) {
            float l = sL[c * 33 + i];
            const float4* v4 = (const float4*)&sh[i * 64];
#pragma unroll
            for (int p = 0; p < 16; p++) {
                float4 v = v4[p];
                acc[4 * p + 0] = fmaf(l, v.x, acc[4 * p + 0]);
                acc[4 * p + 1] = fmaf(l, v.y, acc[4 * p + 1]);
                acc[4 * p + 2] = fmaf(l, v.z, acc[4 * p + 2]);
                acc[4 * p + 3] = fmaf(l, v.w, acc[4 * p + 3]);
            }
        }
    }
    float4* o = (float4*)(out + (size_t)(b * 128 + c) * HW + px0);
#pragma unroll
    for (int p = 0; p < 16; p++)
        o[p] = make_float4(acc[4 * p], acc[4 * p + 1], acc[4 * p + 2], acc[4 * p + 3]);
}

// ---------------------------------------------------------------------------
// Per-channel affine grid_sample (bilinear, zeros padding, align_corners=False)
// multiplied by the BoxPool mask (grid_sample of ones with box theta).
// One block per (b,c); source plane staged in smem.
// ---------------------------------------------------------------------------
template <int H, int W>
__global__ void __launch_bounds__(256) sample_kernel(const float* __restrict__ in,
                                                     float* __restrict__ out,
                                                     const float* __restrict__ geo,
                                                     const float* __restrict__ box) {
    constexpr int HW = H * W;
    __shared__ float sp[HW];
    const int bc = blockIdx.x;
    const int c = bc & 127;
    const float* src = in + (size_t)bc * HW;
    for (int i = threadIdx.x; i < HW; i += 256) sp[i] = src[i];

    const float g0 = geo[c * 6 + 0], g1 = geo[c * 6 + 1], g2 = geo[c * 6 + 2];
    const float g3 = geo[c * 6 + 3], g4 = geo[c * 6 + 4], g5 = geo[c * 6 + 5];
    const float q0 = box[c * 6 + 0], q1 = box[c * 6 + 1], q2 = box[c * 6 + 2];
    const float q3 = box[c * 6 + 3], q4 = box[c * 6 + 4], q5 = box[c * 6 + 5];
    __syncthreads();

    float* dst = out + (size_t)bc * HW;
    for (int i = threadIdx.x; i < HW; i += 256) {
        int h = i / W, w = i % W;
        float xs = (2.f * w + 1.f) * (1.f / W) - 1.f;
        float ys = (2.f * h + 1.f) * (1.f / H) - 1.f;

        // geo sample
        float ix = ((fmaf(g0, xs, fmaf(g1, ys, g2)) + 1.f) * W - 1.f) * 0.5f;
        float iy = ((fmaf(g3, xs, fmaf(g4, ys, g5)) + 1.f) * H - 1.f) * 0.5f;
        float fx = floorf(ix), fy = floorf(iy);
        float wx = ix - fx, wy = iy - fy;
        int x0 = (int)fx, y0 = (int)fy;
        bool xv0 = (x0 >= 0) & (x0 < W), xv1 = (x0 + 1 >= 0) & (x0 + 1 < W);
        bool yv0 = (y0 >= 0) & (y0 < H), yv1 = (y0 + 1 >= 0) & (y0 + 1 < H);
        float v00 = (xv0 & yv0) ? sp[y0 * W + x0] : 0.f;
        float v01 = (xv1 & yv0) ? sp[y0 * W + x0 + 1] : 0.f;
        float v10 = (xv0 & yv1) ? sp[(y0 + 1) * W + x0] : 0.f;
        float v11 = (xv1 & yv1) ? sp[(y0 + 1) * W + x0 + 1] : 0.f;
        float sv = (1.f - wy) * ((1.f - wx) * v00 + wx * v01)
                 + wy * ((1.f - wx) * v10 + wx * v11);

        // box mask (grid_sample of ones)
        float jx = ((fmaf(q0, xs, fmaf(q1, ys, q2)) + 1.f) * W - 1.f) * 0.5f;
        float jy = ((fmaf(q3, xs, fmaf(q4, ys, q5)) + 1.f) * H - 1.f) * 0.5f;
        float bfx = floorf(jx), bfy = floorf(jy);
        float bx = jx - bfx, by = jy - bfy;
        int u0 = (int)bfx, t0 = (int)bfy;
        float m00 = ((u0 >= 0) & (u0 < W) & (t0 >= 0) & (t0 < H)) ? 1.f : 0.f;
        float m01 = ((u0 + 1 >= 0) & (u0 + 1 < W) & (t0 >= 0) & (t0 < H)) ? 1.f : 0.f;
        float m10 = ((u0 >= 0) & (u0 < W) & (t0 + 1 >= 0) & (t0 + 1 < H)) ? 1.f : 0.f;
        float m11 = ((u0 + 1 >= 0) & (u0 + 1 < W) & (t0 + 1 >= 0) & (t0 + 1 < H)) ? 1.f : 0.f;
        float m = (1.f - by) * ((1.f - bx) * m00 + bx * m01)
                + by * ((1.f - bx) * m10 + bx * m11);

        dst[i] = sv * m;
    }
}

// ---------------------------------------------------------------------------
// MaxPool2d_G, k=2, H=W=64: 32x32 box-sum (via integral image) -> argmax
// (first occurrence) -> gather 32x32 window (zero padded) around argmax.
// One block per (b,c) plane.
// ---------------------------------------------------------------------------
__global__ void __launch_bounds__(256) maxpool_kernel(const float* __restrict__ in,
                                                      float* __restrict__ out) {
    __shared__ float sp[4096];        // plane
    __shared__ float sS[64 * 65];     // SAT, padded pitch 65
    __shared__ float rv[256];
    __shared__ int   ri[256];
    const int bc = blockIdx.x;
    const int tid = threadIdx.x;
    const float* src = in + (size_t)bc * 4096;
    for (int i = tid; i < 4096; i += 256) sp[i] = src[i];
    __syncthreads();
    if (tid < 64) {                   // column prefix
        float run = 0.f;
        for (int y = 0; y < 64; y++) { run += sp[y * 64 + tid]; sS[y * 65 + tid] = run; }
    }
    __syncthreads();
    if (tid < 64) {                   // row prefix (in place)
        float run = 0.f;
        for (int x = 0; x < 64; x++) { run += sS[tid * 65 + x]; sS[tid * 65 + x] = run; }
    }
    __syncthreads();

    float bv = -3.4e38f; int bi = 0;
    for (int i = tid; i < 4096; i += 256) {
        int oy = i >> 6, ox = i & 63;
        int y1 = max(oy - 16, 0), y2 = min(oy + 15, 63);
        int x1 = max(ox - 16, 0), x2 = min(ox + 15, 63);
        float s = sS[y2 * 65 + x2];
        if (x1 > 0) s -= sS[y2 * 65 + x1 - 1];
        if (y1 > 0) s -= sS[(y1 - 1) * 65 + x2];
        if (x1 > 0 && y1 > 0) s += sS[(y1 - 1) * 65 + x1 - 1];
        if (s > bv) { bv = s; bi = i; }   // ascending i => first max per thread
    }
    rv[tid] = bv; ri[tid] = bi;
    __syncthreads();
    for (int st = 128; st > 0; st >>= 1) {
        if (tid < st) {
            float ov = rv[tid + st]; int oi = ri[tid + st];
            if (ov > rv[tid] || (ov == rv[tid] && oi < ri[tid])) { rv[tid] = ov; ri[tid] = oi; }
        }
        __syncthreads();
    }
    const int argm = ri[0];
    const int r = argm >> 6, cc = argm & 63;
    for (int i = tid; i < 1024; i += 256) {
        int ii = i >> 5, jj = i & 31;
        int y = r - 16 + ii, x = cc - 16 + jj;
        out[(size_t)bc * 1024 + i] =
            (y >= 0 && y < 64 && x >= 0 && x < 64) ? sp[y * 64 + x] : 0.f;
    }
}

// ---------------------------------------------------------------------------
// Mean over HxW per (b,c)
// ---------------------------------------------------------------------------
__global__ void __launch_bounds__(256) pool_kernel(const float* __restrict__ feat,
                                                   float* __restrict__ pooled) {
    __shared__ float s[256];
    const int bc = blockIdx.x, tid = threadIdx.x;
    const float* f = feat + (size_t)bc * 1024;
    s[tid] = f[tid] + f[tid + 256] + f[tid + 512] + f[tid + 768];
    __syncthreads();
    for (int st = 128; st > 0; st >>= 1) {
        if (tid < st) s[tid] += s[tid + st];
        __syncthreads();
    }
    if (tid == 0) pooled[bc] = s[0] * (1.f / 1024.f);
}

// ---------------------------------------------------------------------------
// Dense head: out[b,o] = pooled[b,:] . dense_w[o,:] + dense_b[o]
// ---------------------------------------------------------------------------
__global__ void dense_kernel(const float* __restrict__ pooled,
                             const float* __restrict__ w,
                             const float* __restrict__ bias,
                             float* __restrict__ out) {
    int t = threadIdx.x;
    if (t < 80) {
        int b = t / 10, o = t % 10;
        float a = bias[o];
        for (int c = 0; c < 128; c++) a = fmaf(pooled[b * 128 + c], w[o * 128 + c], a);
        out[b * 10 + o] = a;
    }
}

extern "C" void kernel_launch(void* const* d_in, const int* in_sizes, int n_in,
                              void* d_out, int out_size) {
    const float* x     = (const float*)d_in[0];
    const float* geo0  = (const float*)d_in[1];
    const float* lin0  = (const float*)d_in[2];
    const float* box0  = (const float*)d_in[3];
    const float* geos  = (const float*)d_in[4];
    const float* lins  = (const float*)d_in[5];
    const float* boxes = (const float*)d_in[6];
    const float* dw    = (const float*)d_in[7];
    const float* db    = (const float*)d_in[8];
    float* out  = (float*)d_out;
    float* feat = out + 80;   // output = concat(out[8,10], feat[8,128,32,32])

    float *y64, *h64, *a32, *b32, *pool;
    cudaGetSymbolAddress((void**)&y64, g_y64);
    cudaGetSymbolAddress((void**)&h64, g_h64);
    cudaGetSymbolAddress((void**)&a32, g_a32);
    cudaGetSymbolAddress((void**)&b32, g_b32);
    cudaGetSymbolAddress((void**)&pool, g_pool);

    // inLay: mix(Ci=3) + sample
    mix3_kernel<<<16384, 256>>>(x, lin0, y64);
    sample_kernel<64, 64><<<1024, 256>>>(y64, h64, geo0, box0);
    // layer 0 (64x64)
    mix128_kernel<4096><<<512, 128>>>(lins + 0 * 16384, h64, y64);
    sample_kernel<64, 64><<<1024, 256>>>(y64, h64, geos + 0 * 768, boxes + 0 * 768);
    // layer 1: maxpool_g
    maxpool_kernel<<<1024, 256>>>(h64, a32);
    // layer 2 (32x32)
    mix128_kernel<1024><<<128, 128>>>(lins + 1 * 16384, a32, b32);
    sample_kernel<32, 32><<<1024, 256>>>(b32, a32, geos + 1 * 768, boxes + 1 * 768);
    // layer 3 (32x32) -> feat
    mix128_kernel<1024><<<128, 128>>>(lins + 2 * 16384, a32, b32);
    sample_kernel<32, 32><<<1024, 256>>>(b32, feat, geos + 2 * 768, boxes + 2 * 768);
    // head
    pool_kernel<<<1024, 256>>>(feat, pool);
    dense_kernel<<<1, 128>>>(pool, dw, db, out);
}

// round 2
// speedup vs baseline: 1.0574x; 1.0574x over previous
#include <cuda_runtime.h>
#include <cuda_bf16.h>

#define BATCH 8
#define CHAN 128

// Scratch (device globals — no allocation allowed)
__device__ float g_y64[BATCH * CHAN * 4096];   // 16 MB
__device__ float g_h64[BATCH * CHAN * 4096];   // 16 MB
__device__ float g_a32[BATCH * CHAN * 1024];   // 4 MB
__device__ float g_b32[BATCH * CHAN * 1024];   // 4 MB
__device__ float g_pool[BATCH * CHAN];

// ---------------------------------------------------------------------------
// 64x64 per-channel affine grid_sample * box mask, 2 batches per block.
// Block = (c, batch-pair). Coordinate/weight/mask math computed ONCE per
// pixel, applied to both batch planes (smem-resident).
// If FUSE3: the source plane is built on the fly as lin0-combination of the
// 3 input channels of x (fuses the input-layer channel mix).
// ---------------------------------------------------------------------------
template <bool FUSE3>
__global__ void __launch_bounds__(256) sample64_kernel(
    const float* __restrict__ in,    // FUSE3: x [8,3,4096]  else [8,128,4096]
    const float* __restrict__ lin,   // [128,3] (FUSE3 only)
    float* __restrict__ out,         // [8,128,4096]
    const float* __restrict__ geo,
    const float* __restrict__ box) {
    constexpr int H = 64, W = 64, HW = 4096;
    __shared__ float sp[2 * HW];
    const int c  = blockIdx.x >> 2;
    const int b0 = (blockIdx.x & 3) * 2;

    if (FUSE3) {
        const float l0 = lin[c * 3 + 0], l1 = lin[c * 3 + 1], l2 = lin[c * 3 + 2];
        for (int j = threadIdx.x; j < 2 * HW; j += 256) {
            int pl = j >> 12, p = j & 4095;
            const float* xb = in + (size_t)(b0 + pl) * 3 * HW + p;
            sp[j] = fmaf(l0, xb[0], fmaf(l1, xb[HW], l2 * xb[2 * HW]));
        }
    } else {
        for (int j = threadIdx.x; j < 2 * HW; j += 256) {
            int pl = j >> 12, p = j & 4095;
            sp[j] = in[((size_t)(b0 + pl) * 128 + c) * HW + p];
        }
    }

    const float g0 = geo[c * 6 + 0], g1 = geo[c * 6 + 1], g2 = geo[c * 6 + 2];
    const float g3 = geo[c * 6 + 3], g4 = geo[c * 6 + 4], g5 = geo[c * 6 + 5];
    const float q0 = box[c * 6 + 0], q1 = box[c * 6 + 1], q2 = box[c * 6 + 2];
    const float q3 = box[c * 6 + 3], q4 = box[c * 6 + 4], q5 = box[c * 6 + 5];
    __syncthreads();

    float* d0 = out + ((size_t)b0 * 128 + c) * HW;
    float* d1 = out + ((size_t)(b0 + 1) * 128 + c) * HW;

    for (int i = threadIdx.x; i < HW; i += 256) {
        int h = i >> 6, w = i & 63;
        float xs = (2.f * w + 1.f) * (1.f / W) - 1.f;
        float ys = (2.f * h + 1.f) * (1.f / H) - 1.f;

        // geo sample coords
        float ix = ((fmaf(g0, xs, fmaf(g1, ys, g2)) + 1.f) * W - 1.f) * 0.5f;
        float iy = ((fmaf(g3, xs, fmaf(g4, ys, g5)) + 1.f) * H - 1.f) * 0.5f;
        float fx = floorf(ix), fy = floorf(iy);
        float wx = ix - fx, wy = iy - fy;
        int x0 = (int)fx, y0 = (int)fy;
        float vx0 = (x0 >= 0 && x0 < W) ? 1.f : 0.f;
        float vx1 = (x0 + 1 >= 0 && x0 + 1 < W) ? 1.f : 0.f;
        float vy0 = (y0 >= 0 && y0 < H) ? 1.f : 0.f;
        float vy1 = (y0 + 1 >= 0 && y0 + 1 < H) ? 1.f : 0.f;
        float ax0 = (1.f - wx) * vx0, ax1 = wx * vx1;
        float ay0 = (1.f - wy) * vy0, ay1 = wy * vy1;

        // box mask (separable: validity = xvalid & yvalid)
        float jx = ((fmaf(q0, xs, fmaf(q1, ys, q2)) + 1.f) * W - 1.f) * 0.5f;
        float jy = ((fmaf(q3, xs, fmaf(q4, ys, q5)) + 1.f) * H - 1.f) * 0.5f;
        float bfx = floorf(jx), bfy = floorf(jy);
        float bx = jx - bfx, by = jy - bfy;
        int u0 = (int)bfx, t0 = (int)bfy;
        float mx = (1.f - bx) * ((u0 >= 0 && u0 < W) ? 1.f : 0.f)
                 + bx * ((u0 + 1 >= 0 && u0 + 1 < W) ? 1.f : 0.f);
        float my = (1.f - by) * ((t0 >= 0 && t0 < H) ? 1.f : 0.f)
                 + by * ((t0 + 1 >= 0 && t0 + 1 < H) ? 1.f : 0.f);
        float m = mx * my;

        // weights premultiplied by validity and mask
        float w00 = ax0 * ay0 * m, w01 = ax1 * ay0 * m;
        float w10 = ax0 * ay1 * m, w11 = ax1 * ay1 * m;

        int xc0 = min(max(x0, 0), W - 1), xc1 = min(max(x0 + 1, 0), W - 1);
        int yc0 = min(max(y0, 0), H - 1), yc1 = min(max(y0 + 1, 0), H - 1);
        int i00 = yc0 * W + xc0, i01 = yc0 * W + xc1;
        int i10 = yc1 * W + xc0, i11 = yc1 * W + xc1;

        d0[i] = w00 * sp[i00] + w01 * sp[i01] + w10 * sp[i10] + w11 * sp[i11];
        d1[i] = w00 * sp[HW + i00] + w01 * sp[HW + i01]
              + w10 * sp[HW + i10] + w11 * sp[HW + i11];
    }
}

// ---------------------------------------------------------------------------
// 32x32 sample, all 8 batches per block (block = channel). Coordinate math
// once per pixel, 8 gathers. Optionally fuses the global mean-pool.
// ---------------------------------------------------------------------------
template <bool POOL>
__global__ void __launch_bounds__(256) sample32_kernel(
    const float* __restrict__ in, float* __restrict__ out,
    const float* __restrict__ geo, const float* __restrict__ box,
    float* __restrict__ pooled) {
    constexpr int H = 32, W = 32, HW = 1024;
    __shared__ float sp[8 * HW];     // 32 KB
    __shared__ float red[64];
    const int c = blockIdx.x;
    for (int j = threadIdx.x; j < 8 * HW; j += 256) {
        int b = j >> 10, p = j & 1023;
        sp[j] = in[((size_t)b * 128 + c) * HW + p];
    }
    const float g0 = geo[c * 6 + 0], g1 = geo[c * 6 + 1], g2 = geo[c * 6 + 2];
    const float g3 = geo[c * 6 + 3], g4 = geo[c * 6 + 4], g5 = geo[c * 6 + 5];
    const float q0 = box[c * 6 + 0], q1 = box[c * 6 + 1], q2 = box[c * 6 + 2];
    const float q3 = box[c * 6 + 3], q4 = box[c * 6 + 4], q5 = box[c * 6 + 5];
    __syncthreads();

    float psum[8];
#pragma unroll
    for (int b = 0; b < 8; b++) psum[b] = 0.f;

    for (int i = threadIdx.x; i < HW; i += 256) {
        int h = i >> 5, w = i & 31;
        float xs = (2.f * w + 1.f) * (1.f / W) - 1.f;
        float ys = (2.f * h + 1.f) * (1.f / H) - 1.f;

        float ix = ((fmaf(g0, xs, fmaf(g1, ys, g2)) + 1.f) * W - 1.f) * 0.5f;
        float iy = ((fmaf(g3, xs, fmaf(g4, ys, g5)) + 1.f) * H - 1.f) * 0.5f;
        float fx = floorf(ix), fy = floorf(iy);
        float wx = ix - fx, wy = iy - fy;
        int x0 = (int)fx, y0 = (int)fy;
        float vx0 = (x0 >= 0 && x0 < W) ? 1.f : 0.f;
        float vx1 = (x0 + 1 >= 0 && x0 + 1 < W) ? 1.f : 0.f;
        float vy0 = (y0 >= 0 && y0 < H) ? 1.f : 0.f;
        float vy1 = (y0 + 1 >= 0 && y0 + 1 < H) ? 1.f : 0.f;
        float ax0 = (1.f - wx) * vx0, ax1 = wx * vx1;
        float ay0 = (1.f - wy) * vy0, ay1 = wy * vy1;

        float jx = ((fmaf(q0, xs, fmaf(q1, ys, q2)) + 1.f) * W - 1.f) * 0.5f;
        float jy = ((fmaf(q3, xs, fmaf(q4, ys, q5)) + 1.f) * H - 1.f) * 0.5f;
        float bfx = floorf(jx), bfy = floorf(jy);
        float bx = jx - bfx, by = jy - bfy;
        int u0 = (int)bfx, t0 = (int)bfy;
        float mx = (1.f - bx) * ((u0 >= 0 && u0 < W) ? 1.f : 0.f)
                 + bx * ((u0 + 1 >= 0 && u0 + 1 < W) ? 1.f : 0.f);
        float my = (1.f - by) * ((t0 >= 0 && t0 < H) ? 1.f : 0.f)
                 + by * ((t0 + 1 >= 0 && t0 + 1 < H) ? 1.f : 0.f);
        float m = mx * my;

        float w00 = ax0 * ay0 * m, w01 = ax1 * ay0 * m;
        float w10 = ax0 * ay1 * m, w11 = ax1 * ay1 * m;

        int xc0 = min(max(x0, 0), W - 1), xc1 = min(max(x0 + 1, 0), W - 1);
        int yc0 = min(max(y0, 0), H - 1), yc1 = min(max(y0 + 1, 0), H - 1);
        int i00 = yc0 * W + xc0, i01 = yc0 * W + xc1;
        int i10 = yc1 * W + xc0, i11 = yc1 * W + xc1;

#pragma unroll
        for (int b = 0; b < 8; b++) {
            const float* p = sp + b * HW;
            float s = w00 * p[i00] + w01 * p[i01] + w10 * p[i10] + w11 * p[i11];
            out[((size_t)b * 128 + c) * HW + i] = s;
            if (POOL) psum[b] += s;
        }
    }

    if (POOL) {
        int lane = threadIdx.x & 31, wid = threadIdx.x >> 5;
#pragma unroll
        for (int b = 0; b < 8; b++) {
            float v = psum[b];
            v += __shfl_down_sync(0xffffffff, v, 16);
            v += __shfl_down_sync(0xffffffff, v, 8);
            v += __shfl_down_sync(0xffffffff, v, 4);
            v += __shfl_down_sync(0xffffffff, v, 2);
            v += __shfl_down_sync(0xffffffff, v, 1);
            if (lane == 0) red[wid * 8 + b] = v;
        }
        __syncthreads();
        if (threadIdx.x < 8) {
            float s = 0.f;
#pragma unroll
            for (int w2 = 0; w2 < 8; w2++) s += red[w2 * 8 + threadIdx.x];
            pooled[threadIdx.x * 128 + c] = s * (1.f / 1024.f);
        }
    }
}

// ---------------------------------------------------------------------------
// Channel mix 128x128 with packed fma.rn.f32x2 (2 FMAs per FFMA2 issue).
// Thread = output channel, 64 pixels per block; acc kept as 32 f32x2 pairs.
// ---------------------------------------------------------------------------
template <int HW>
__global__ void __launch_bounds__(128) mix128_kernel(const float* __restrict__ L,
                                                     const float* __restrict__ in,
                                                     float* __restrict__ out) {
    __shared__ float sL[128 * 33];
    __shared__ float sh[32 * 64];
    const int tilesPerImg = HW / 64;
    const int b = blockIdx.x / tilesPerImg;
    const int px0 = (blockIdx.x % tilesPerImg) * 64;
    const int c = threadIdx.x;

    unsigned long long acc[32];
#pragma unroll
    for (int p = 0; p < 32; p++) acc[p] = 0ULL;

    for (int q = 0; q < 4; q++) {
        __syncthreads();
#pragma unroll
        for (int k = 0; k < 32; k++) {
            int idx = k * 128 + c;
            int cc = idx >> 5, ii = idx & 31;
            sL[cc * 33 + ii] = L[cc * 128 + q * 32 + ii];
        }
#pragma unroll
        for (int k = 0; k < 16; k++) {
            int idx = k * 128 + c;
            int ii = idx >> 6, pp = idx & 63;
            sh[idx] = in[((size_t)b * 128 + q * 32 + ii) * HW + px0 + pp];
        }
        __syncthreads();
#pragma unroll 2
        for (int i = 0; i < 32; i++) {
            unsigned lo = __float_as_uint(sL[c * 33 + i]);
            unsigned long long lp;
            asm("mov.b64 %0, {%1, %1};" : "=l"(lp) : "r"(lo));
            const ulonglong2* v2 = (const ulonglong2*)&sh[i * 64];
#pragma unroll
            for (int p = 0; p < 16; p++) {
                ulonglong2 v = v2[p];
                asm("fma.rn.f32x2 %0, %1, %2, %0;" : "+l"(acc[2 * p])     : "l"(lp), "l"(v.x));
                asm("fma.rn.f32x2 %0, %1, %2, %0;" : "+l"(acc[2 * p + 1]) : "l"(lp), "l"(v.y));
            }
        }
    }
    ulonglong2* o = (ulonglong2*)(out + ((size_t)b * 128 + c) * HW + px0);
#pragma unroll
    for (int p = 0; p < 16; p++) o[p] = make_ulonglong2(acc[2 * p], acc[2 * p + 1]);
}

// ---------------------------------------------------------------------------
// MaxPool2d_G, k=2, H=W=64 (unchanged from R1: SAT -> argmax -> gather)
// ---------------------------------------------------------------------------
__global__ void __launch_bounds__(256) maxpool_kernel(const float* __restrict__ in,
                                                      float* __restrict__ out) {
    __shared__ float sp[4096];
    __shared__ float sS[64 * 65];
    __shared__ float rv[256];
    __shared__ int   ri[256];
    const int bc = blockIdx.x;
    const int tid = threadIdx.x;
    const float* src = in + (size_t)bc * 4096;
    for (int i = tid; i < 4096; i += 256) sp[i] = src[i];
    __syncthreads();
    if (tid < 64) {
        float run = 0.f;
        for (int y = 0; y < 64; y++) { run += sp[y * 64 + tid]; sS[y * 65 + tid] = run; }
    }
    __syncthreads();
    if (tid < 64) {
        float run = 0.f;
        for (int x = 0; x < 64; x++) { run += sS[tid * 65 + x]; sS[tid * 65 + x] = run; }
    }
    __syncthreads();

    float bv = -3.4e38f; int bi = 0;
    for (int i = tid; i < 4096; i += 256) {
        int oy = i >> 6, ox = i & 63;
        int y1 = max(oy - 16, 0), y2 = min(oy + 15, 63);
        int x1 = max(ox - 16, 0), x2 = min(ox + 15, 63);
        float s = sS[y2 * 65 + x2];
        if (x1 > 0) s -= sS[y2 * 65 + x1 - 1];
        if (y1 > 0) s -= sS[(y1 - 1) * 65 + x2];
        if (x1 > 0 && y1 > 0) s += sS[(y1 - 1) * 65 + x1 - 1];
        if (s > bv) { bv = s; bi = i; }
    }
    rv[tid] = bv; ri[tid] = bi;
    __syncthreads();
    for (int st = 128; st > 0; st >>= 1) {
        if (tid < st) {
            float ov = rv[tid + st]; int oi = ri[tid + st];
            if (ov > rv[tid] || (ov == rv[tid] && oi < ri[tid])) { rv[tid] = ov; ri[tid] = oi; }
        }
        __syncthreads();
    }
    const int argm = ri[0];
    const int r = argm >> 6, cc = argm & 63;
    for (int i = tid; i < 1024; i += 256) {
        int ii = i >> 5, jj = i & 31;
        int y = r - 16 + ii, x = cc - 16 + jj;
        out[(size_t)bc * 1024 + i] =
            (y >= 0 && y < 64 && x >= 0 && x < 64) ? sp[y * 64 + x] : 0.f;
    }
}

// ---------------------------------------------------------------------------
// Dense head
// ---------------------------------------------------------------------------
__global__ void dense_kernel(const float* __restrict__ pooled,
                             const float* __restrict__ w,
                             const float* __restrict__ bias,
                             float* __restrict__ out) {
    int t = threadIdx.x;
    if (t < 80) {
        int b = t / 10, o = t % 10;
        float a = bias[o];
        for (int c = 0; c < 128; c++) a = fmaf(pooled[b * 128 + c], w[o * 128 + c], a);
        out[b * 10 + o] = a;
    }
}

extern "C" void kernel_launch(void* const* d_in, const int* in_sizes, int n_in,
                              void* d_out, int out_size) {
    const float* x     = (const float*)d_in[0];
    const float* geo0  = (const float*)d_in[1];
    const float* lin0  = (const float*)d_in[2];
    const float* box0  = (const float*)d_in[3];
    const float* geos  = (const float*)d_in[4];
    const float* lins  = (const float*)d_in[5];
    const float* boxes = (const float*)d_in[6];
    const float* dw    = (const float*)d_in[7];
    const float* db    = (const float*)d_in[8];
    float* out  = (float*)d_out;
    float* feat = out + 80;   // output = concat(out[8,10], feat[8,128,32,32])

    float *y64, *h64, *a32, *b32, *pool;
    cudaGetSymbolAddress((void**)&y64, g_y64);
    cudaGetSymbolAddress((void**)&h64, g_h64);
    cudaGetSymbolAddress((void**)&a32, g_a32);
    cudaGetSymbolAddress((void**)&b32, g_b32);
    cudaGetSymbolAddress((void**)&pool, g_pool);

    // inLay: fused mix3 + sample
    sample64_kernel<true><<<512, 256>>>(x, lin0, h64, geo0, box0);
    // layer 0 (64x64)
    mix128_kernel<4096><<<512, 128>>>(lins + 0 * 16384, h64, y64);
    sample64_kernel<false><<<512, 256>>>(y64, nullptr, h64, geos + 0 * 768, boxes + 0 * 768);
    // layer 1: maxpool_g
    maxpool_kernel<<<1024, 256>>>(h64, a32);
    // layer 2 (32x32)
    mix128_kernel<1024><<<128, 128>>>(lins + 1 * 16384, a32, b32);
    sample32_kernel<false><<<128, 256>>>(b32, a32, geos + 1 * 768, boxes + 1 * 768, nullptr);
    // layer 3 (32x32) -> feat (+ fused mean pool)
    mix128_kernel<1024><<<128, 128>>>(lins + 2 * 16384, a32, b32);
    sample32_kernel<true><<<128, 256>>>(b32, feat, geos + 2 * 768, boxes + 2 * 768, pool);
    // head
    dense_kernel<<<1, 128>>>(pool, dw, db, out);
}

// round 3
// speedup vs baseline: 1.4585x; 1.3792x over previous
#include <cuda_runtime.h>
#include <cuda_bf16.h>

#define BATCH 8
#define CHAN 128

__device__ float g_y64[BATCH * CHAN * 4096];   // 16 MB
__device__ float g_h64[BATCH * CHAN * 4096];   // 16 MB
__device__ float g_a32[BATCH * CHAN * 1024];   // 4 MB
__device__ float g_b32[BATCH * CHAN * 1024];   // 4 MB
__device__ float g_pool[BATCH * CHAN];

// ---------------------------------------------------------------------------
// 64x64 grid_sample * box mask, 4 batches per block (dynamic smem 64KB).
// Coordinate/weight/mask math once per pixel, applied to 4 planes.
// FUSE3: source plane built on the fly from the 3 input channels (input mix).
// ---------------------------------------------------------------------------
template <bool FUSE3>
__global__ void __launch_bounds__(256) sample64_kernel(
    const float* __restrict__ in, const float* __restrict__ lin,
    float* __restrict__ out,
    const float* __restrict__ geo, const float* __restrict__ box) {
    constexpr int H = 64, W = 64, HW = 4096;
    extern __shared__ float sp[];              // 4 * HW
    const int c  = blockIdx.x >> 1;
    const int b0 = (blockIdx.x & 1) * 4;

    if (FUSE3) {
        const float l0 = lin[c * 3 + 0], l1 = lin[c * 3 + 1], l2 = lin[c * 3 + 2];
        for (int j = threadIdx.x; j < 4 * HW; j += 256) {
            int pl = j >> 12, p = j & 4095;
            const float* xb = in + (size_t)(b0 + pl) * 3 * HW + p;
            sp[j] = fmaf(l0, xb[0], fmaf(l1, xb[HW], l2 * xb[2 * HW]));
        }
    } else {
        for (int j = threadIdx.x; j < 4 * HW; j += 256) {
            int pl = j >> 12, p = j & 4095;
            sp[j] = in[((size_t)(b0 + pl) * 128 + c) * HW + p];
        }
    }

    const float g0 = geo[c * 6 + 0], g1 = geo[c * 6 + 1], g2 = geo[c * 6 + 2];
    const float g3 = geo[c * 6 + 3], g4 = geo[c * 6 + 4], g5 = geo[c * 6 + 5];
    const float q0 = box[c * 6 + 0], q1 = box[c * 6 + 1], q2 = box[c * 6 + 2];
    const float q3 = box[c * 6 + 3], q4 = box[c * 6 + 4], q5 = box[c * 6 + 5];
    __syncthreads();

    float* d0 = out + ((size_t)b0 * 128 + c) * HW;

    for (int i = threadIdx.x; i < HW; i += 256) {
        int h = i >> 6, w = i & 63;
        float xs = (2.f * w + 1.f) * (1.f / W) - 1.f;
        float ys = (2.f * h + 1.f) * (1.f / H) - 1.f;

        float ix = ((fmaf(g0, xs, fmaf(g1, ys, g2)) + 1.f) * W - 1.f) * 0.5f;
        float iy = ((fmaf(g3, xs, fmaf(g4, ys, g5)) + 1.f) * H - 1.f) * 0.5f;
        float fx = floorf(ix), fy = floorf(iy);
        float wx = ix - fx, wy = iy - fy;
        int x0 = (int)fx, y0 = (int)fy;
        float vx0 = (x0 >= 0 && x0 < W) ? 1.f : 0.f;
        float vx1 = (x0 + 1 >= 0 && x0 + 1 < W) ? 1.f : 0.f;
        float vy0 = (y0 >= 0 && y0 < H) ? 1.f : 0.f;
        float vy1 = (y0 + 1 >= 0 && y0 + 1 < H) ? 1.f : 0.f;
        float ax0 = (1.f - wx) * vx0, ax1 = wx * vx1;
        float ay0 = (1.f - wy) * vy0, ay1 = wy * vy1;

        float jx = ((fmaf(q0, xs, fmaf(q1, ys, q2)) + 1.f) * W - 1.f) * 0.5f;
        float jy = ((fmaf(q3, xs, fmaf(q4, ys, q5)) + 1.f) * H - 1.f) * 0.5f;
        float bfx = floorf(jx), bfy = floorf(jy);
        float bx = jx - bfx, by = jy - bfy;
        int u0 = (int)bfx, t0 = (int)bfy;
        float mx = (1.f - bx) * ((u0 >= 0 && u0 < W) ? 1.f : 0.f)
                 + bx * ((u0 + 1 >= 0 && u0 + 1 < W) ? 1.f : 0.f);
        float my = (1.f - by) * ((t0 >= 0 && t0 < H) ? 1.f : 0.f)
                 + by * ((t0 + 1 >= 0 && t0 + 1 < H) ? 1.f : 0.f);
        float m = mx * my;

        float w00 = ax0 * ay0 * m, w01 = ax1 * ay0 * m;
        float w10 = ax0 * ay1 * m, w11 = ax1 * ay1 * m;

        int xc0 = min(max(x0, 0), W - 1), xc1 = min(max(x0 + 1, 0), W - 1);
        int yc0 = min(max(y0, 0), H - 1), yc1 = min(max(y0 + 1, 0), H - 1);
        int i00 = yc0 * W + xc0, i01 = yc0 * W + xc1;
        int i10 = yc1 * W + xc0, i11 = yc1 * W + xc1;

#pragma unroll
        for (int pl = 0; pl < 4; pl++) {
            const float* p = sp + pl * HW;
            d0[pl * (size_t)128 * HW + i] =
                w00 * p[i00] + w01 * p[i01] + w10 * p[i10] + w11 * p[i11];
        }
    }
}

// ---------------------------------------------------------------------------
// 32x32 sample, all 8 batches per block. Optionally fuses the mean-pool.
// ---------------------------------------------------------------------------
template <bool POOL>
__global__ void __launch_bounds__(256) sample32_kernel(
    const float* __restrict__ in, float* __restrict__ out,
    const float* __restrict__ geo, const float* __restrict__ box,
    float* __restrict__ pooled) {
    constexpr int H = 32, W = 32, HW = 1024;
    __shared__ float sp[8 * HW];
    __shared__ float red[64];
    const int c = blockIdx.x;
    for (int j = threadIdx.x; j < 8 * HW; j += 256) {
        int b = j >> 10, p = j & 1023;
        sp[j] = in[((size_t)b * 128 + c) * HW + p];
    }
    const float g0 = geo[c * 6 + 0], g1 = geo[c * 6 + 1], g2 = geo[c * 6 + 2];
    const float g3 = geo[c * 6 + 3], g4 = geo[c * 6 + 4], g5 = geo[c * 6 + 5];
    const float q0 = box[c * 6 + 0], q1 = box[c * 6 + 1], q2 = box[c * 6 + 2];
    const float q3 = box[c * 6 + 3], q4 = box[c * 6 + 4], q5 = box[c * 6 + 5];
    __syncthreads();

    float psum[8];
#pragma unroll
    for (int b = 0; b < 8; b++) psum[b] = 0.f;

    for (int i = threadIdx.x; i < HW; i += 256) {
        int h = i >> 5, w = i & 31;
        float xs = (2.f * w + 1.f) * (1.f / W) - 1.f;
        float ys = (2.f * h + 1.f) * (1.f / H) - 1.f;

        float ix = ((fmaf(g0, xs, fmaf(g1, ys, g2)) + 1.f) * W - 1.f) * 0.5f;
        float iy = ((fmaf(g3, xs, fmaf(g4, ys, g5)) + 1.f) * H - 1.f) * 0.5f;
        float fx = floorf(ix), fy = floorf(iy);
        float wx = ix - fx, wy = iy - fy;
        int x0 = (int)fx, y0 = (int)fy;
        float vx0 = (x0 >= 0 && x0 < W) ? 1.f : 0.f;
        float vx1 = (x0 + 1 >= 0 && x0 + 1 < W) ? 1.f : 0.f;
        float vy0 = (y0 >= 0 && y0 < H) ? 1.f : 0.f;
        float vy1 = (y0 + 1 >= 0 && y0 + 1 < H) ? 1.f : 0.f;
        float ax0 = (1.f - wx) * vx0, ax1 = wx * vx1;
        float ay0 = (1.f - wy) * vy0, ay1 = wy * vy1;

        float jx = ((fmaf(q0, xs, fmaf(q1, ys, q2)) + 1.f) * W - 1.f) * 0.5f;
        float jy = ((fmaf(q3, xs, fmaf(q4, ys, q5)) + 1.f) * H - 1.f) * 0.5f;
        float bfx = floorf(jx), bfy = floorf(jy);
        float bx = jx - bfx, by = jy - bfy;
        int u0 = (int)bfx, t0 = (int)bfy;
        float mx = (1.f - bx) * ((u0 >= 0 && u0 < W) ? 1.f : 0.f)
                 + bx * ((u0 + 1 >= 0 && u0 + 1 < W) ? 1.f : 0.f);
        float my = (1.f - by) * ((t0 >= 0 && t0 < H) ? 1.f : 0.f)
                 + by * ((t0 + 1 >= 0 && t0 + 1 < H) ? 1.f : 0.f);
        float m = mx * my;

        float w00 = ax0 * ay0 * m, w01 = ax1 * ay0 * m;
        float w10 = ax0 * ay1 * m, w11 = ax1 * ay1 * m;

        int xc0 = min(max(x0, 0), W - 1), xc1 = min(max(x0 + 1, 0), W - 1);
        int yc0 = min(max(y0, 0), H - 1), yc1 = min(max(y0 + 1, 0), H - 1);
        int i00 = yc0 * W + xc0, i01 = yc0 * W + xc1;
        int i10 = yc1 * W + xc0, i11 = yc1 * W + xc1;

#pragma unroll
        for (int b = 0; b < 8; b++) {
            const float* p = sp + b * HW;
            float s = w00 * p[i00] + w01 * p[i01] + w10 * p[i10] + w11 * p[i11];
            out[((size_t)b * 128 + c) * HW + i] = s;
            if (POOL) psum[b] += s;
        }
    }

    if (POOL) {
        int lane = threadIdx.x & 31, wid = threadIdx.x >> 5;
#pragma unroll
        for (int b = 0; b < 8; b++) {
            float v = psum[b];
            v += __shfl_down_sync(0xffffffff, v, 16);
            v += __shfl_down_sync(0xffffffff, v, 8);
            v += __shfl_down_sync(0xffffffff, v, 4);
            v += __shfl_down_sync(0xffffffff, v, 2);
            v += __shfl_down_sync(0xffffffff, v, 1);
            if (lane == 0) red[wid * 8 + b] = v;
        }
        __syncthreads();
        if (threadIdx.x < 8) {
            float s = 0.f;
#pragma unroll
            for (int w2 = 0; w2 < 8; w2++) s += red[w2 * 8 + threadIdx.x];
            pooled[threadIdx.x * 128 + c] = s * (1.f / 1024.f);
        }
    }
}

// ---------------------------------------------------------------------------
// Register-tiled channel-mix GEMM: out[b,c,p] = sum_i L[c,i] * in[b,i,p].
// Tile: 128 channels x TN pixels, K=128 in chunks of 16. 256 threads; each
// thread computes CPT channels x 8 pixels with f32x2 accumulators
// (channel pairs in the two lanes).
// ---------------------------------------------------------------------------
template <int HW, int TN, int CPT>
__global__ void __launch_bounds__(256, 2) mixgemm_kernel(
    const float* __restrict__ L, const float* __restrict__ in,
    float* __restrict__ out) {
    constexpr int KC = 16;
    __shared__ float sL[KC][128];
    __shared__ float sIn[KC][TN];
    constexpr int NGROUP = TN / 8;
    const int tiles = HW / TN;
    const int b = blockIdx.x / tiles;
    const int px0 = (blockIdx.x % tiles) * TN;
    const int tid = threadIdx.x;
    const int tn = tid % NGROUP;
    const int tm = tid / NGROUP;
    const int c0 = tm * CPT;
    const int p0 = tn * 8;

    unsigned long long acc[CPT / 2][8];
#pragma unroll
    for (int i = 0; i < CPT / 2; i++)
#pragma unroll
        for (int j = 0; j < 8; j++) acc[i][j] = 0ULL;

    for (int k0 = 0; k0 < 128; k0 += KC) {
        __syncthreads();
        {   // L chunk: KC x 128 (sL[k][c] = L[c][k0+k])
            int lc = tid >> 1, kk = (tid & 1) * 8;
            float4 v0 = *(const float4*)&L[lc * 128 + k0 + kk];
            float4 v1 = *(const float4*)&L[lc * 128 + k0 + kk + 4];
            sL[kk + 0][lc] = v0.x; sL[kk + 1][lc] = v0.y;
            sL[kk + 2][lc] = v0.z; sL[kk + 3][lc] = v0.w;
            sL[kk + 4][lc] = v1.x; sL[kk + 5][lc] = v1.y;
            sL[kk + 6][lc] = v1.z; sL[kk + 7][lc] = v1.w;
        }
        if (TN == 128) {   // In chunk: 2048 floats, 8/thread
            int k = tid >> 4, pp = (tid & 15) * 8;
            const float* src = in + ((size_t)b * 128 + k0 + k) * HW + px0 + pp;
            *(float4*)&sIn[k][pp]     = *(const float4*)src;
            *(float4*)&sIn[k][pp + 4] = *(const float4*)(src + 4);
        } else {           // TN==64: 1024 floats, 4/thread
            int k = tid >> 4, pp = (tid & 15) * 4;
            const float* src = in + ((size_t)b * 128 + k0 + k) * HW + px0 + pp;
            *(float4*)&sIn[k][pp] = *(const float4*)src;
        }
        __syncthreads();

#pragma unroll
        for (int k = 0; k < KC; k++) {
            unsigned long long av[CPT / 2];
            {
                ulonglong2 a01 = *(const ulonglong2*)&sL[k][c0];
                av[0] = a01.x; av[1] = a01.y;
                if (CPT == 8) {
                    ulonglong2 a23 = *(const ulonglong2*)&sL[k][c0 + 4];
                    av[2] = a23.x; av[3] = a23.y;
                }
            }
            float4 bv0 = *(const float4*)&sIn[k][p0];
            float4 bv1 = *(const float4*)&sIn[k][p0 + 4];
            float bp[8] = {bv0.x, bv0.y, bv0.z, bv0.w, bv1.x, bv1.y, bv1.z, bv1.w};
            unsigned long long bb[8];
#pragma unroll
            for (int j = 0; j < 8; j++) {
                unsigned r = __float_as_uint(bp[j]);
                asm("mov.b64 %0, {%1, %1};" : "=l"(bb[j]) : "r"(r));
            }
#pragma unroll
            for (int cc = 0; cc < CPT / 2; cc++)
#pragma unroll
                for (int j = 0; j < 8; j++)
                    asm("fma.rn.f32x2 %0, %1, %2, %0;"
                        : "+l"(acc[cc][j]) : "l"(av[cc]), "l"(bb[j]));
        }
    }

#pragma unroll
    for (int cc = 0; cc < CPT / 2; cc++) {
        float lo[8], hi[8];
#pragma unroll
        for (int j = 0; j < 8; j++)
            asm("mov.b64 {%0, %1}, %2;" : "=r"(*(unsigned*)&lo[j]),
                "=r"(*(unsigned*)&hi[j]) : "l"(acc[cc][j]));
        float* r0 = out + ((size_t)b * 128 + c0 + 2 * cc) * HW + px0 + p0;
        float* r1 = r0 + HW;
        *(float4*)r0       = make_float4(lo[0], lo[1], lo[2], lo[3]);
        *(float4*)(r0 + 4) = make_float4(lo[4], lo[5], lo[6], lo[7]);
        *(float4*)r1       = make_float4(hi[0], hi[1], hi[2], hi[3]);
        *(float4*)(r1 + 4) = make_float4(hi[4], hi[5], hi[6], hi[7]);
    }
}

// ---------------------------------------------------------------------------
// MaxPool2d_G k=2, 64x64: separable windowed box-sum via warp-shuffle prefix
// scans (log-depth), argmax (first index), gather 32x32 window (zero pad).
// ---------------------------------------------------------------------------
__global__ void __launch_bounds__(256) maxpool_kernel(const float* __restrict__ in,
                                                      float* __restrict__ out) {
    __shared__ float sp[4096];      // plane, pitch 64
    __shared__ float A[64 * 65];    // prefix / windowed sums, pitch 65
    __shared__ float rv[256];
    __shared__ int   ri[256];
    const int bc = blockIdx.x;
    const int tid = threadIdx.x;
    const int lane = tid & 31, wid = tid >> 5;
    const float* src = in + (size_t)bc * 4096;
    for (int i = tid; i < 4096; i += 256) sp[i] = src[i];
    __syncthreads();

    // Row pass: prefix scan + horizontal window diff (rows owned per warp)
#pragma unroll
    for (int r = 0; r < 8; r++) {
        int y = wid * 8 + r;
        float e0 = sp[y * 64 + 2 * lane], e1 = sp[y * 64 + 2 * lane + 1];
        float s = e0 + e1;
#pragma unroll
        for (int off = 1; off < 32; off <<= 1) {
            float t = __shfl_up_sync(0xffffffffu, s, off);
            if (lane >= off) s += t;
        }
        float excl = s - (e0 + e1);
        A[y * 65 + 2 * lane] = excl + e0;
        A[y * 65 + 2 * lane + 1] = s;
        __syncwarp();
        int xA = 2 * lane, xB = 2 * lane + 1;
        float hiA = A[y * 65 + min(xA + 15, 63)];
        float loA = (xA >= 17) ? A[y * 65 + xA - 17] : 0.f;
        float hiB = A[y * 65 + min(xB + 15, 63)];
        float loB = (xB >= 17) ? A[y * 65 + xB - 17] : 0.f;
        __syncwarp();
        A[y * 65 + xA] = hiA - loA;
        A[y * 65 + xB] = hiB - loB;
        __syncwarp();
    }
    __syncthreads();

    // Column pass: prefix scan along y (columns owned per warp), in place
#pragma unroll
    for (int r = 0; r < 8; r++) {
        int x = wid * 8 + r;
        float e0 = A[(2 * lane) * 65 + x], e1 = A[(2 * lane + 1) * 65 + x];
        float s = e0 + e1;
#pragma unroll
        for (int off = 1; off < 32; off <<= 1) {
            float t = __shfl_up_sync(0xffffffffu, s, off);
            if (lane >= off) s += t;
        }
        float excl = s - (e0 + e1);
        __syncwarp();
        A[(2 * lane) * 65 + x] = excl + e0;
        A[(2 * lane + 1) * 65 + x] = s;
        __syncwarp();
    }
    __syncthreads();

    // Vertical window diff fused into argmax (first-index tie-break)
    float bv = -3.4e38f; int bi = 0;
    for (int i = tid; i < 4096; i += 256) {
        int oy = i >> 6, ox = i & 63;
        float top = A[min(oy + 15, 63) * 65 + ox];
        float bot = (oy >= 17) ? A[(oy - 17) * 65 + ox] : 0.f;
        float s = top - bot;
        if (s > bv) { bv = s; bi = i; }
    }
    rv[tid] = bv; ri[tid] = bi;
    __syncthreads();
    for (int st = 128; st > 0; st >>= 1) {
        if (tid < st) {
            float ov = rv[tid + st]; int oi = ri[tid + st];
            if (ov > rv[tid] || (ov == rv[tid] && oi < ri[tid])) { rv[tid] = ov; ri[tid] = oi; }
        }
        __syncthreads();
    }
    const int argm = ri[0];
    const int r0 = argm >> 6, c0 = argm & 63;
    for (int i = tid; i < 1024; i += 256) {
        int ii = i >> 5, jj = i & 31;
        int y = r0 - 16 + ii, x = c0 - 16 + jj;
        out[(size_t)bc * 1024 + i] =
            (y >= 0 && y < 64 && x >= 0 && x < 64) ? sp[y * 64 + x] : 0.f;
    }
}

// ---------------------------------------------------------------------------
// Dense head
// ---------------------------------------------------------------------------
__global__ void dense_kernel(const float* __restrict__ pooled,
                             const float* __restrict__ w,
                             const float* __restrict__ bias,
                             float* __restrict__ out) {
    int t = threadIdx.x;
    if (t < 80) {
        int b = t / 10, o = t % 10;
        float a = bias[o];
        for (int c = 0; c < 128; c++) a = fmaf(pooled[b * 128 + c], w[o * 128 + c], a);
        out[b * 10 + o] = a;
    }
}

extern "C" void kernel_launch(void* const* d_in, const int* in_sizes, int n_in,
                              void* d_out, int out_size) {
    const float* x     = (const float*)d_in[0];
    const float* geo0  = (const float*)d_in[1];
    const float* lin0  = (const float*)d_in[2];
    const float* box0  = (const float*)d_in[3];
    const float* geos  = (const float*)d_in[4];
    const float* lins  = (const float*)d_in[5];
    const float* boxes = (const float*)d_in[6];
    const float* dw    = (const float*)d_in[7];
    const float* db    = (const float*)d_in[8];
    float* out  = (float*)d_out;
    float* feat = out + 80;   // output = concat(out[8,10], feat[8,128,32,32])

    float *y64, *h64, *a32, *b32, *pool;
    cudaGetSymbolAddress((void**)&y64, g_y64);
    cudaGetSymbolAddress((void**)&h64, g_h64);
    cudaGetSymbolAddress((void**)&a32, g_a32);
    cudaGetSymbolAddress((void**)&b32, g_b32);
    cudaGetSymbolAddress((void**)&pool, g_pool);

    const int smem64 = 4 * 4096 * sizeof(float);   // 64 KB
    cudaFuncSetAttribute(sample64_kernel<true>,
                         cudaFuncAttributeMaxDynamicSharedMemorySize, smem64);
    cudaFuncSetAttribute(sample64_kernel<false>,
                         cudaFuncAttributeMaxDynamicSharedMemorySize, smem64);

    // inLay: fused mix3 + sample (64x64)
    sample64_kernel<true><<<256, 256, smem64>>>(x, lin0, h64, geo0, box0);
    // layer 0 (64x64)
    mixgemm_kernel<4096, 128, 8><<<256, 256>>>(lins + 0 * 16384, h64, y64);
    sample64_kernel<false><<<256, 256, smem64>>>(y64, nullptr, h64,
                                                 geos + 0 * 768, boxes + 0 * 768);
    // layer 1: maxpool_g
    maxpool_kernel<<<1024, 256>>>(h64, a32);
    // layer 2 (32x32)
    mixgemm_kernel<1024, 64, 4><<<128, 256>>>(lins + 1 * 16384, a32, b32);
    sample32_kernel<false><<<128, 256>>>(b32, a32, geos + 1 * 768, boxes + 1 * 768, nullptr);
    // layer 3 (32x32) -> feat (+ fused mean pool)
    mixgemm_kernel<1024, 64, 4><<<128, 256>>>(lins + 2 * 16384, a32, b32);
    sample32_kernel<true><<<128, 256>>>(b32, feat, geos + 2 * 768, boxes + 2 * 768, pool);
    // head
    dense_kernel<<<1, 128>>>(pool, dw, db, out);
}

// round 4
// speedup vs baseline: 1.5650x; 1.0731x over previous
#include <cuda_runtime.h>
#include <cuda_bf16.h>

#define BATCH 8
#define CHAN 128

__device__ float g_y64[BATCH * CHAN * 4096];   // 16 MB
__device__ float g_h64[BATCH * CHAN * 4096];   // 16 MB
__device__ float g_a32[BATCH * CHAN * 1024];   // 4 MB
__device__ float g_b32[BATCH * CHAN * 1024];   // 4 MB
__device__ float g_pool[BATCH * CHAN];

// ---------------------------------------------------------------------------
// 64x64 grid_sample * box mask, 4 batches per block (dynamic smem 64KB).
// ---------------------------------------------------------------------------
template <bool FUSE3>
__global__ void __launch_bounds__(256) sample64_kernel(
    const float* __restrict__ in, const float* __restrict__ lin,
    float* __restrict__ out,
    const float* __restrict__ geo, const float* __restrict__ box) {
    constexpr int H = 64, W = 64, HW = 4096;
    extern __shared__ float sp[];              // 4 * HW
    const int c  = blockIdx.x >> 1;
    const int b0 = (blockIdx.x & 1) * 4;

    if (FUSE3) {
        const float l0 = lin[c * 3 + 0], l1 = lin[c * 3 + 1], l2 = lin[c * 3 + 2];
        for (int j = threadIdx.x; j < 4 * HW; j += 256) {
            int pl = j >> 12, p = j & 4095;
            const float* xb = in + (size_t)(b0 + pl) * 3 * HW + p;
            sp[j] = fmaf(l0, xb[0], fmaf(l1, xb[HW], l2 * xb[2 * HW]));
        }
    } else {
        for (int j = threadIdx.x; j < 4 * HW; j += 256) {
            int pl = j >> 12, p = j & 4095;
            sp[j] = in[((size_t)(b0 + pl) * 128 + c) * HW + p];
        }
    }

    const float g0 = geo[c * 6 + 0], g1 = geo[c * 6 + 1], g2 = geo[c * 6 + 2];
    const float g3 = geo[c * 6 + 3], g4 = geo[c * 6 + 4], g5 = geo[c * 6 + 5];
    const float q0 = box[c * 6 + 0], q1 = box[c * 6 + 1], q2 = box[c * 6 + 2];
    const float q3 = box[c * 6 + 3], q4 = box[c * 6 + 4], q5 = box[c * 6 + 5];
    __syncthreads();

    float* d0 = out + ((size_t)b0 * 128 + c) * HW;

    for (int i = threadIdx.x; i < HW; i += 256) {
        int h = i >> 6, w = i & 63;
        float xs = (2.f * w + 1.f) * (1.f / W) - 1.f;
        float ys = (2.f * h + 1.f) * (1.f / H) - 1.f;

        float ix = ((fmaf(g0, xs, fmaf(g1, ys, g2)) + 1.f) * W - 1.f) * 0.5f;
        float iy = ((fmaf(g3, xs, fmaf(g4, ys, g5)) + 1.f) * H - 1.f) * 0.5f;
        float fx = floorf(ix), fy = floorf(iy);
        float wx = ix - fx, wy = iy - fy;
        int x0 = (int)fx, y0 = (int)fy;
        float vx0 = (x0 >= 0 && x0 < W) ? 1.f : 0.f;
        float vx1 = (x0 + 1 >= 0 && x0 + 1 < W) ? 1.f : 0.f;
        float vy0 = (y0 >= 0 && y0 < H) ? 1.f : 0.f;
        float vy1 = (y0 + 1 >= 0 && y0 + 1 < H) ? 1.f : 0.f;
        float ax0 = (1.f - wx) * vx0, ax1 = wx * vx1;
        float ay0 = (1.f - wy) * vy0, ay1 = wy * vy1;

        float jx = ((fmaf(q0, xs, fmaf(q1, ys, q2)) + 1.f) * W - 1.f) * 0.5f;
        float jy = ((fmaf(q3, xs, fmaf(q4, ys, q5)) + 1.f) * H - 1.f) * 0.5f;
        float bfx = floorf(jx), bfy = floorf(jy);
        float bx = jx - bfx, by = jy - bfy;
        int u0 = (int)bfx, t0 = (int)bfy;
        float mx = (1.f - bx) * ((u0 >= 0 && u0 < W) ? 1.f : 0.f)
                 + bx * ((u0 + 1 >= 0 && u0 + 1 < W) ? 1.f : 0.f);
        float my = (1.f - by) * ((t0 >= 0 && t0 < H) ? 1.f : 0.f)
                 + by * ((t0 + 1 >= 0 && t0 + 1 < H) ? 1.f : 0.f);
        float m = mx * my;

        float w00 = ax0 * ay0 * m, w01 = ax1 * ay0 * m;
        float w10 = ax0 * ay1 * m, w11 = ax1 * ay1 * m;

        int xc0 = min(max(x0, 0), W - 1), xc1 = min(max(x0 + 1, 0), W - 1);
        int yc0 = min(max(y0, 0), H - 1), yc1 = min(max(y0 + 1, 0), H - 1);
        int i00 = yc0 * W + xc0, i01 = yc0 * W + xc1;
        int i10 = yc1 * W + xc0, i11 = yc1 * W + xc1;

#pragma unroll
        for (int pl = 0; pl < 4; pl++) {
            const float* p = sp + pl * HW;
            d0[pl * (size_t)128 * HW + i] =
                w00 * p[i00] + w01 * p[i01] + w10 * p[i10] + w11 * p[i11];
        }
    }
}

// ---------------------------------------------------------------------------
// 32x32 sample, all 8 batches per block. Optionally fuses the mean-pool.
// ---------------------------------------------------------------------------
template <bool POOL>
__global__ void __launch_bounds__(256) sample32_kernel(
    const float* __restrict__ in, float* __restrict__ out,
    const float* __restrict__ geo, const float* __restrict__ box,
    float* __restrict__ pooled) {
    constexpr int H = 32, W = 32, HW = 1024;
    __shared__ float sp[8 * HW];
    __shared__ float red[64];
    const int c = blockIdx.x;
    for (int j = threadIdx.x; j < 8 * HW; j += 256) {
        int b = j >> 10, p = j & 1023;
        sp[j] = in[((size_t)b * 128 + c) * HW + p];
    }
    const float g0 = geo[c * 6 + 0], g1 = geo[c * 6 + 1], g2 = geo[c * 6 + 2];
    const float g3 = geo[c * 6 + 3], g4 = geo[c * 6 + 4], g5 = geo[c * 6 + 5];
    const float q0 = box[c * 6 + 0], q1 = box[c * 6 + 1], q2 = box[c * 6 + 2];
    const float q3 = box[c * 6 + 3], q4 = box[c * 6 + 4], q5 = box[c * 6 + 5];
    __syncthreads();

    float psum[8];
#pragma unroll
    for (int b = 0; b < 8; b++) psum[b] = 0.f;

    for (int i = threadIdx.x; i < HW; i += 256) {
        int h = i >> 5, w = i & 31;
        float xs = (2.f * w + 1.f) * (1.f / W) - 1.f;
        float ys = (2.f * h + 1.f) * (1.f / H) - 1.f;

        float ix = ((fmaf(g0, xs, fmaf(g1, ys, g2)) + 1.f) * W - 1.f) * 0.5f;
        float iy = ((fmaf(g3, xs, fmaf(g4, ys, g5)) + 1.f) * H - 1.f) * 0.5f;
        float fx = floorf(ix), fy = floorf(iy);
        float wx = ix - fx, wy = iy - fy;
        int x0 = (int)fx, y0 = (int)fy;
        float vx0 = (x0 >= 0 && x0 < W) ? 1.f : 0.f;
        float vx1 = (x0 + 1 >= 0 && x0 + 1 < W) ? 1.f : 0.f;
        float vy0 = (y0 >= 0 && y0 < H) ? 1.f : 0.f;
        float vy1 = (y0 + 1 >= 0 && y0 + 1 < H) ? 1.f : 0.f;
        float ax0 = (1.f - wx) * vx0, ax1 = wx * vx1;
        float ay0 = (1.f - wy) * vy0, ay1 = wy * vy1;

        float jx = ((fmaf(q0, xs, fmaf(q1, ys, q2)) + 1.f) * W - 1.f) * 0.5f;
        float jy = ((fmaf(q3, xs, fmaf(q4, ys, q5)) + 1.f) * H - 1.f) * 0.5f;
        float bfx = floorf(jx), bfy = floorf(jy);
        float bx = jx - bfx, by = jy - bfy;
        int u0 = (int)bfx, t0 = (int)bfy;
        float mx = (1.f - bx) * ((u0 >= 0 && u0 < W) ? 1.f : 0.f)
                 + bx * ((u0 + 1 >= 0 && u0 + 1 < W) ? 1.f : 0.f);
        float my = (1.f - by) * ((t0 >= 0 && t0 < H) ? 1.f : 0.f)
                 + by * ((t0 + 1 >= 0 && t0 + 1 < H) ? 1.f : 0.f);
        float m = mx * my;

        float w00 = ax0 * ay0 * m, w01 = ax1 * ay0 * m;
        float w10 = ax0 * ay1 * m, w11 = ax1 * ay1 * m;

        int xc0 = min(max(x0, 0), W - 1), xc1 = min(max(x0 + 1, 0), W - 1);
        int yc0 = min(max(y0, 0), H - 1), yc1 = min(max(y0 + 1, 0), H - 1);
        int i00 = yc0 * W + xc0, i01 = yc0 * W + xc1;
        int i10 = yc1 * W + xc0, i11 = yc1 * W + xc1;

#pragma unroll
        for (int b = 0; b < 8; b++) {
            const float* p = sp + b * HW;
            float s = w00 * p[i00] + w01 * p[i01] + w10 * p[i10] + w11 * p[i11];
            out[((size_t)b * 128 + c) * HW + i] = s;
            if (POOL) psum[b] += s;
        }
    }

    if (POOL) {
        int lane = threadIdx.x & 31, wid = threadIdx.x >> 5;
#pragma unroll
        for (int b = 0; b < 8; b++) {
            float v = psum[b];
            v += __shfl_down_sync(0xffffffff, v, 16);
            v += __shfl_down_sync(0xffffffff, v, 8);
            v += __shfl_down_sync(0xffffffff, v, 4);
            v += __shfl_down_sync(0xffffffff, v, 2);
            v += __shfl_down_sync(0xffffffff, v, 1);
            if (lane == 0) red[wid * 8 + b] = v;
        }
        __syncthreads();
        if (threadIdx.x < 8) {
            float s = 0.f;
#pragma unroll
            for (int w2 = 0; w2 < 8; w2++) s += red[w2 * 8 + threadIdx.x];
            pooled[threadIdx.x * 128 + c] = s * (1.f / 1024.f);
        }
    }
}

// ---------------------------------------------------------------------------
// Register-tiled channel-mix GEMM with f32x2 accumulators.
// ---------------------------------------------------------------------------
template <int HW, int TN, int CPT>
__global__ void __launch_bounds__(256, 2) mixgemm_kernel(
    const float* __restrict__ L, const float* __restrict__ in,
    float* __restrict__ out) {
    constexpr int KC = 16;
    __shared__ float sL[KC][128];
    __shared__ float sIn[KC][TN];
    constexpr int NGROUP = TN / 8;
    const int tiles = HW / TN;
    const int b = blockIdx.x / tiles;
    const int px0 = (blockIdx.x % tiles) * TN;
    const int tid = threadIdx.x;
    const int tn = tid % NGROUP;
    const int tm = tid / NGROUP;
    const int c0 = tm * CPT;
    const int p0 = tn * 8;

    unsigned long long acc[CPT / 2][8];
#pragma unroll
    for (int i = 0; i < CPT / 2; i++)
#pragma unroll
        for (int j = 0; j < 8; j++) acc[i][j] = 0ULL;

    for (int k0 = 0; k0 < 128; k0 += KC) {
        __syncthreads();
        {
            int lc = tid >> 1, kk = (tid & 1) * 8;
            float4 v0 = *(const float4*)&L[lc * 128 + k0 + kk];
            float4 v1 = *(const float4*)&L[lc * 128 + k0 + kk + 4];
            sL[kk + 0][lc] = v0.x; sL[kk + 1][lc] = v0.y;
            sL[kk + 2][lc] = v0.z; sL[kk + 3][lc] = v0.w;
            sL[kk + 4][lc] = v1.x; sL[kk + 5][lc] = v1.y;
            sL[kk + 6][lc] = v1.z; sL[kk + 7][lc] = v1.w;
        }
        if (TN == 128) {
            int k = tid >> 4, pp = (tid & 15) * 8;
            const float* src = in + ((size_t)b * 128 + k0 + k) * HW + px0 + pp;
            *(float4*)&sIn[k][pp]     = *(const float4*)src;
            *(float4*)&sIn[k][pp + 4] = *(const float4*)(src + 4);
        } else {
            int k = tid >> 4, pp = (tid & 15) * 4;
            const float* src = in + ((size_t)b * 128 + k0 + k) * HW + px0 + pp;
            *(float4*)&sIn[k][pp] = *(const float4*)src;
        }
        __syncthreads();

#pragma unroll
        for (int k = 0; k < KC; k++) {
            unsigned long long av[CPT / 2];
            {
                ulonglong2 a01 = *(const ulonglong2*)&sL[k][c0];
                av[0] = a01.x; av[1] = a01.y;
                if (CPT == 8) {
                    ulonglong2 a23 = *(const ulonglong2*)&sL[k][c0 + 4];
                    av[2] = a23.x; av[3] = a23.y;
                }
            }
            float4 bv0 = *(const float4*)&sIn[k][p0];
            float4 bv1 = *(const float4*)&sIn[k][p0 + 4];
            float bp[8] = {bv0.x, bv0.y, bv0.z, bv0.w, bv1.x, bv1.y, bv1.z, bv1.w};
            unsigned long long bb[8];
#pragma unroll
            for (int j = 0; j < 8; j++) {
                unsigned r = __float_as_uint(bp[j]);
                asm("mov.b64 %0, {%1, %1};" : "=l"(bb[j]) : "r"(r));
            }
#pragma unroll
            for (int cc = 0; cc < CPT / 2; cc++)
#pragma unroll
                for (int j = 0; j < 8; j++)
                    asm("fma.rn.f32x2 %0, %1, %2, %0;"
                        : "+l"(acc[cc][j]) : "l"(av[cc]), "l"(bb[j]));
        }
    }

#pragma unroll
    for (int cc = 0; cc < CPT / 2; cc++) {
        float lo[8], hi[8];
#pragma unroll
        for (int j = 0; j < 8; j++)
            asm("mov.b64 {%0, %1}, %2;" : "=r"(*(unsigned*)&lo[j]),
                "=r"(*(unsigned*)&hi[j]) : "l"(acc[cc][j]));
        float* r0 = out + ((size_t)b * 128 + c0 + 2 * cc) * HW + px0 + p0;
        float* r1 = r0 + HW;
        *(float4*)r0       = make_float4(lo[0], lo[1], lo[2], lo[3]);
        *(float4*)(r0 + 4) = make_float4(lo[4], lo[5], lo[6], lo[7]);
        *(float4*)r1       = make_float4(hi[0], hi[1], hi[2], hi[3]);
        *(float4*)(r1 + 4) = make_float4(hi[4], hi[5], hi[6], hi[7]);
    }
}

// ---------------------------------------------------------------------------
// MaxPool2d_G k=2, 64x64. 4 planes per block; every phase uses all 256 thr.
//  phase 1: column prefix (thread = (plane, col), gmem reads, L2-hot)
//  phase 2: row prefix in smem (thread = (plane, row))
//  phase 3: vertical window diff + argmax (thread = (plane, out-row)),
//           first-index tie-break preserved
//  phase 4: gather 32x32 window from gmem (zero pad)
// smem: SAT only (4 x 64 x 65 floats = 66.5 KB, dynamic).
// ---------------------------------------------------------------------------
__global__ void __launch_bounds__(256) maxpool_kernel(const float* __restrict__ in,
                                                      float* __restrict__ out) {
    extern __shared__ float A[];               // 4 * 4160
    __shared__ float rb[8];
    __shared__ int   ib[8];
    __shared__ int   argm[4];
    const int tid = threadIdx.x;
    const int pl = tid >> 6;                   // 0..3
    const int t = tid & 63;
    const int base = blockIdx.x * 4;
    float* Ap = A + pl * 4160;
    const float* src = in + (size_t)(base + pl) * 4096;

    // phase 1: column prefix sums (x = t)
    {
        float run = 0.f;
#pragma unroll 8
        for (int y = 0; y < 64; y++) {
            run += __ldg(&src[y * 64 + t]);
            Ap[y * 65 + t] = run;
        }
    }
    __syncthreads();

    // phase 2: row prefix sums (y = t), in place
    {
        float run = 0.f;
        float* row = Ap + t * 65;
#pragma unroll 8
        for (int x = 0; x < 64; x++) {
            run += row[x];
            row[x] = run;
        }
    }
    __syncthreads();

    // phase 3: windowed sums + argmax; thread owns output row oy = t
    {
        const int oy = t;
        const float* rowHi = Ap + min(oy + 15, 63) * 65;
        const float* rowLo = Ap + (oy - 17) * 65;      // only read if oy>=17
        const bool hasLo = (oy >= 17);
        float bv = -3.4e38f; int bi = 0;
#pragma unroll 8
        for (int ox = 0; ox < 64; ox++) {
            int x2 = min(ox + 15, 63);
            float s = rowHi[x2];
            if (ox >= 17) s -= rowHi[ox - 17];
            if (hasLo) {
                s -= rowLo[x2];
                if (ox >= 17) s += rowLo[ox - 17];
            }
            if (s > bv) { bv = s; bi = oy * 64 + ox; }
        }
        // reduce 64 threads (2 warps) per plane, prefer lower index on ties
        int lane = tid & 31;
#pragma unroll
        for (int off = 16; off > 0; off >>= 1) {
            float ov = __shfl_down_sync(0xffffffffu, bv, off);
            int oi = __shfl_down_sync(0xffffffffu, bi, off);
            if (ov > bv || (ov == bv && oi < bi)) { bv = ov; bi = oi; }
        }
        if (lane == 0) { rb[tid >> 5] = bv; ib[tid >> 5] = bi; }
    }
    __syncthreads();
    if (t == 0) {
        float v0 = rb[pl * 2], v1 = rb[pl * 2 + 1];
        int i0 = ib[pl * 2], i1 = ib[pl * 2 + 1];
        argm[pl] = (v1 > v0 || (v1 == v0 && i1 < i0)) ? i1 : i0;
    }
    __syncthreads();

    // phase 4: gather 32x32 window around argmax (zero padding), from gmem
    for (int j = tid; j < 4096; j += 256) {
        int p2 = j >> 10, i = j & 1023;
        int am = argm[p2];
        int r0 = am >> 6, c0 = am & 63;
        int ii = i >> 5, jj = i & 31;
        int y = r0 - 16 + ii, x = c0 - 16 + jj;
        float v = 0.f;
        if (y >= 0 && y < 64 && x >= 0 && x < 64)
            v = __ldg(&in[(size_t)(base + p2) * 4096 + y * 64 + x]);
        out[(size_t)(base + p2) * 1024 + i] = v;
    }
}

// ---------------------------------------------------------------------------
// Dense head
// ---------------------------------------------------------------------------
__global__ void dense_kernel(const float* __restrict__ pooled,
                             const float* __restrict__ w,
                             const float* __restrict__ bias,
                             float* __restrict__ out) {
    int t = threadIdx.x;
    if (t < 80) {
        int b = t / 10, o = t % 10;
        float a = bias[o];
        for (int c = 0; c < 128; c++) a = fmaf(pooled[b * 128 + c], w[o * 128 + c], a);
        out[b * 10 + o] = a;
    }
}

extern "C" void kernel_launch(void* const* d_in, const int* in_sizes, int n_in,
                              void* d_out, int out_size) {
    const float* x     = (const float*)d_in[0];
    const float* geo0  = (const float*)d_in[1];
    const float* lin0  = (const float*)d_in[2];
    const float* box0  = (const float*)d_in[3];
    const float* geos  = (const float*)d_in[4];
    const float* lins  = (const float*)d_in[5];
    const float* boxes = (const float*)d_in[6];
    const float* dw    = (const float*)d_in[7];
    const float* db    = (const float*)d_in[8];
    float* out  = (float*)d_out;
    float* feat = out + 80;

    float *y64, *h64, *a32, *b32, *pool;
    cudaGetSymbolAddress((void**)&y64, g_y64);
    cudaGetSymbolAddress((void**)&h64, g_h64);
    cudaGetSymbolAddress((void**)&a32, g_a32);
    cudaGetSymbolAddress((void**)&b32, g_b32);
    cudaGetSymbolAddress((void**)&pool, g_pool);

    const int smem64 = 4 * 4096 * sizeof(float);    // 64 KB
    const int smemMP = 4 * 4160 * sizeof(float);    // 66.5 KB
    cudaFuncSetAttribute(sample64_kernel<true>,
                         cudaFuncAttributeMaxDynamicSharedMemorySize, smem64);
    cudaFuncSetAttribute(sample64_kernel<false>,
                         cudaFuncAttributeMaxDynamicSharedMemorySize, smem64);
    cudaFuncSetAttribute(maxpool_kernel,
                         cudaFuncAttributeMaxDynamicSharedMemorySize, smemMP);

    // inLay: fused mix3 + sample (64x64)
    sample64_kernel<true><<<256, 256, smem64>>>(x, lin0, h64, geo0, box0);
    // layer 0 (64x64)
    mixgemm_kernel<4096, 128, 8><<<256, 256>>>(lins + 0 * 16384, h64, y64);
    sample64_kernel<false><<<256, 256, smem64>>>(y64, nullptr, h64,
                                                 geos + 0 * 768, boxes + 0 * 768);
    // layer 1: maxpool_g (4 planes/block)
    maxpool_kernel<<<256, 256, smemMP>>>(h64, a32);
    // layer 2 (32x32)
    mixgemm_kernel<1024, 64, 4><<<128, 256>>>(lins + 1 * 16384, a32, b32);
    sample32_kernel<false><<<128, 256>>>(b32, a32, geos + 1 * 768, boxes + 1 * 768, nullptr);
    // layer 3 (32x32) -> feat (+ fused mean pool)
    mixgemm_kernel<1024, 64, 4><<<128, 256>>>(lins + 2 * 16384, a32, b32);
    sample32_kernel<true><<<128, 256>>>(b32, feat, geos + 2 * 768, boxes + 2 * 768, pool);
    // head
    dense_kernel<<<1, 128>>>(pool, dw, db, out);
}